// round 13
// baseline (speedup 1.0000x reference)
#include <cuda_runtime.h>
#include <cuda_fp16.h>
#include <cstdint>

#define BATCH 64
#define TIME  2048
#define FEAT  256
#define MROWS (BATCH * TIME)
#define EPS_V 1e-7f

// ---------------- scratch (static device globals; alloc-free rule) ----------
__device__ __half g_Wh[FEAT * FEAT];             // g_Wh[n*FEAT+k] = (half)W[k][n]
__device__ float  g_part[(MROWS / 128) * FEAT];  // per-CTA numerator partials
__device__ float  g_denp[MROWS / 128];           // per-CTA denominator partials

__device__ __forceinline__ uint32_t h2_as_u32(__half2 h) {
    return *reinterpret_cast<uint32_t*>(&h);
}
__device__ __forceinline__ uint32_t smem_u32(const void* p) {
    uint32_t a;
    asm("{ .reg .u64 t; cvta.to.shared.u64 t, %1; cvt.u32.u64 %0, t; }" : "=r"(a) : "l"(p));
    return a;
}
template<int N> __device__ __forceinline__ void cpwait() {
    asm volatile("cp.async.wait_group %0;" :: "n"(N) : "memory");
}

// ---------------- k0: tiled transpose W[k][n] -> g_Wh[n][k] (half) ----------
__global__ __launch_bounds__(1024)
void k0_wh(const float* __restrict__ W) {
    __shared__ float t[32][33];
    const int tx = threadIdx.x, ty = threadIdx.y;
    const int x0 = blockIdx.x * 32, y0 = blockIdx.y * 32;
    t[ty][tx] = W[(y0 + ty) * FEAT + x0 + tx];
    __syncthreads();
    g_Wh[(x0 + ty) * FEAT + y0 + tx] = __float2half_rn(t[tx][ty]);
}

// ---------------- k1: fp16 mma GEMM + tanh + u-dot + exp + weighted-x -------
#define BM 128
#define BN 256
#define BK 64
#define KT (FEAT / BK)          // 4
#define K1_THREADS 512          // 16 warps: wm = wid%4 (32 M-rows), wn = wid/4 (64 N-cols)

#define A_STRIDE 528            // 256 halfs + 16B pad; LDSM 8-row phase conflict-free
#define A_FULL   (BM * A_STRIDE)          // 67584 : full fp16 A tile, resident
#define B_OFF    A_FULL
#define B_STRIDE 144
#define B_STAGE  (BN * B_STRIDE)          // 36864 per kt stage
#define SMEM_SZ  (B_OFF + KT * B_STAGE)   // 215040
// epilogue scratch overlays B stage 0 (all stage-0 reads complete by then)
#define RED_OFF  B_OFF                    // red[512] floats
#define ES_OFF   (B_OFF + 2048)           // e_s[128]
#define WP_OFF   (B_OFF + 2560)           // wp[4]

__device__ __forceinline__ void mma_f16(float* d, const uint32_t* a, uint32_t b0, uint32_t b1) {
    asm volatile(
        "mma.sync.aligned.m16n8k16.row.col.f32.f16.f16.f32 "
        "{%0,%1,%2,%3}, {%4,%5,%6,%7}, {%8,%9}, {%0,%1,%2,%3};"
        : "+f"(d[0]), "+f"(d[1]), "+f"(d[2]), "+f"(d[3])
        : "r"(a[0]), "r"(a[1]), "r"(a[2]), "r"(a[3]), "r"(b0), "r"(b1));
}
__device__ __forceinline__ void ldsm4(uint32_t* d, uint32_t addr) {
    asm volatile("ldmatrix.sync.aligned.m8n8.x4.shared.b16 {%0,%1,%2,%3}, [%4];"
                 : "=r"(d[0]), "=r"(d[1]), "=r"(d[2]), "=r"(d[3]) : "r"(addr));
}

__global__ __launch_bounds__(K1_THREADS, 1)
void k1_mma(const float* __restrict__ x, const float* __restrict__ bias,
            const float* __restrict__ u)
{
    extern __shared__ char smem[];
    const uint32_t sb = smem_u32(smem);
    const int tid = threadIdx.x;
    const int wid = tid >> 5, l = tid & 31;
    const int wm = wid & 3, wn = wid >> 2;      // wm: 32 M-rows; wn: 64 N-cols
    const int lq = l >> 2, lr = l & 3;
    const size_t rowBase = (size_t)blockIdx.x * BM;

    // ldmatrix per-thread source offsets
    const uint32_t aOff = (uint32_t)((wm * 32 + (l & 7) + ((l >> 3) & 1) * 8) * A_STRIDE
                                     + ((l >> 4) & 1) * 16);
    const uint32_t bRel = (uint32_t)((wn * 64 + (l & 7) + ((l >> 4) & 1) * 8) * B_STRIDE
                                     + ((l >> 3) & 1) * 16);

    float acc[2][8][4];
    #pragma unroll
    for (int mt = 0; mt < 2; mt++)
        #pragma unroll
        for (int nt = 0; nt < 8; nt++)
            #pragma unroll
            for (int c = 0; c < 4; c++) acc[mt][nt][c] = 0.0f;

    // ---- prologue: issue ALL B cp.asyncs (4 stages, 4 commit groups) -------
    #pragma unroll
    for (int kt = 0; kt < KT; kt++) {
        #pragma unroll
        for (int i = 0; i < 4; i++) {
            const int ch = tid + i * K1_THREADS;
            const int n = ch >> 3, q = ch & 7;
            const uint32_t dst = sb + B_OFF + kt * B_STAGE + n * B_STRIDE + q * 16;
            asm volatile("cp.async.cg.shared.global [%0], [%1], 16;"
                         :: "r"(dst), "l"(g_Wh + n * FEAT + kt * BK + q * 8) : "memory");
        }
        asm volatile("cp.async.commit_group;" ::: "memory");
    }

    // ---- prologue: load FULL A tile (128 rows x 64 float4), 16 per thread --
    #pragma unroll
    for (int i = 0; i < 2; i++) {
        float4 v[8];
        #pragma unroll
        for (int j = 0; j < 8; j++) {
            const int idx = tid + (i * 8 + j) * K1_THREADS;   // 0..8191
            const int row = idx >> 6, q = idx & 63;
            v[j] = *reinterpret_cast<const float4*>(&x[(rowBase + row) * FEAT + q * 4]);
        }
        #pragma unroll
        for (int j = 0; j < 8; j++) {
            const int idx = tid + (i * 8 + j) * K1_THREADS;
            const int row = idx >> 6, q = idx & 63;
            const uint32_t h0 = h2_as_u32(__floats2half2_rn(v[j].x, v[j].y));
            const uint32_t h1 = h2_as_u32(__floats2half2_rn(v[j].z, v[j].w));
            *reinterpret_cast<uint2*>(smem + row * A_STRIDE + q * 8) = make_uint2(h0, h1);
        }
    }

    // ---- mainloop: pure LDSM + HMMA, one barrier per kt --------------------
    #pragma unroll
    for (int kt = 0; kt < KT; kt++) {
        if      (kt == 0) cpwait<3>();
        else if (kt == 1) cpwait<2>();
        else if (kt == 2) cpwait<1>();
        else              cpwait<0>();
        __syncthreads();

        const uint32_t bStage = sb + B_OFF + kt * B_STAGE + bRel;
        #pragma unroll
        for (int ks = 0; ks < 4; ks++) {
            uint32_t af[2][4];
            #pragma unroll
            for (int mt = 0; mt < 2; mt++)
                ldsm4(af[mt], sb + aOff + mt * 16 * A_STRIDE + kt * (BK * 2) + ks * 32);
            #pragma unroll
            for (int p = 0; p < 4; p++) {
                uint32_t bf[4];
                ldsm4(bf, bStage + p * 16 * B_STRIDE + ks * 32);
                #pragma unroll
                for (int mt = 0; mt < 2; mt++) {
                    mma_f16(acc[mt][2 * p],     af[mt], bf[0], bf[1]);
                    mma_f16(acc[mt][2 * p + 1], af[mt], bf[2], bf[3]);
                }
            }
        }
    }

    // ---- epilogue stage 1: tanh + u-dot, reduce to per-row ait -------------
    float bv[16], uv[16];
    #pragma unroll
    for (int nt = 0; nt < 8; nt++)
        #pragma unroll
        for (int d = 0; d < 2; d++) {
            const int col = wn * 64 + nt * 8 + lr * 2 + d;
            bv[nt * 2 + d] = bias[col];
            uv[nt * 2 + d] = u[col];
        }

    float* red = reinterpret_cast<float*>(smem + RED_OFF);
    float* e_s = reinterpret_cast<float*>(smem + ES_OFF);
    float* wp  = reinterpret_cast<float*>(smem + WP_OFF);
    #pragma unroll
    for (int mt = 0; mt < 2; mt++) {
        float p0 = 0.0f, p1 = 0.0f;
        #pragma unroll
        for (int nt = 0; nt < 8; nt++)
            #pragma unroll
            for (int d = 0; d < 2; d++) {
                {
                    const float v = acc[mt][nt][d] + bv[nt * 2 + d];
                    const float t = 1.0f - __fdividef(2.0f, __expf(v + v) + 1.0f);
                    p0 = fmaf(t, uv[nt * 2 + d], p0);
                }
                {
                    const float v = acc[mt][nt][2 + d] + bv[nt * 2 + d];
                    const float t = 1.0f - __fdividef(2.0f, __expf(v + v) + 1.0f);
                    p1 = fmaf(t, uv[nt * 2 + d], p1);
                }
            }
        #pragma unroll
        for (int off = 2; off > 0; off >>= 1) {
            p0 += __shfl_xor_sync(0xffffffffu, p0, off);
            p1 += __shfl_xor_sync(0xffffffffu, p1, off);
        }
        if (lr == 0) {
            red[wn * BM + wm * 32 + mt * 16 + lq]     = p0;
            red[wn * BM + wm * 32 + mt * 16 + lq + 8] = p1;
        }
    }
    __syncthreads();

    // ---- epilogue stage 2: e = exp(ait); denominator partial ---------------
    if (tid < BM) {
        const float s = red[tid] + red[BM + tid] + red[2 * BM + tid] + red[3 * BM + tid];
        const float e = expf(s);
        e_s[tid] = e;
        float w = e;
        #pragma unroll
        for (int off = 16; off > 0; off >>= 1)
            w += __shfl_xor_sync(0xffffffffu, w, off);
        if (l == 0) wp[wid] = w;
    }
    __syncthreads();
    if (tid == 0)
        g_denp[blockIdx.x] = wp[0] + wp[1] + wp[2] + wp[3];

    // ---- epilogue stage 3: numerator from RESIDENT fp16 A tile (no gmem) ---
    {
        const int col = tid & 255;
        const int rowgrp = tid >> 8;              // rows 0..63 / 64..127
        float a0 = 0.0f, a1 = 0.0f;
        #pragma unroll 8
        for (int i = 0; i < 64; i += 2) {
            const int r0 = rowgrp * 64 + i;
            const float x0 = __half2float(*reinterpret_cast<const __half*>(
                smem + r0 * A_STRIDE + col * 2));
            const float x1 = __half2float(*reinterpret_cast<const __half*>(
                smem + (r0 + 1) * A_STRIDE + col * 2));
            a0 = fmaf(x0, e_s[r0], a0);
            a1 = fmaf(x1, e_s[r0 + 1], a1);
        }
        red[tid] = a0 + a1;
    }
    __syncthreads();
    if (tid < FEAT)
        g_part[blockIdx.x * FEAT + tid] = red[tid] + red[FEAT + tid];
}

// ---------------- k_final: out[b,f] = num/(den+eps) -------------------------
#define CTAS_PER_B (TIME / BM)   // 16
__global__ __launch_bounds__(256)
void k_final(float* __restrict__ out) {
    const int b = blockIdx.x, tid = threadIdx.x;
    float den = 0.0f;
    #pragma unroll
    for (int i = 0; i < CTAS_PER_B; i++)
        den += g_denp[b * CTAS_PER_B + i];
    float num = 0.0f;
    #pragma unroll
    for (int i = 0; i < CTAS_PER_B; i++)
        num += g_part[(b * CTAS_PER_B + i) * FEAT + tid];
    out[b * FEAT + tid] = num / (den + EPS_V);
}

// ---------------------------------------------------------------------------
extern "C" void kernel_launch(void* const* d_in, const int* in_sizes, int n_in,
                              void* d_out, int out_size) {
    const float* x = (const float*)d_in[0];
    const float* W = (const float*)d_in[1];
    const float* b = (const float*)d_in[2];
    const float* u = (const float*)d_in[3];
    float* out = (float*)d_out;

    cudaFuncSetAttribute(k1_mma, cudaFuncAttributeMaxDynamicSharedMemorySize, SMEM_SZ);

    dim3 tb(32, 32);
    dim3 tg(FEAT / 32, FEAT / 32);
    k0_wh<<<tg, tb>>>(W);
    k1_mma<<<MROWS / BM, K1_THREADS, SMEM_SZ>>>(x, b, u);
    k_final<<<BATCH, FEAT>>>(out);
}

// round 16
// speedup vs baseline: 1.0881x; 1.0881x over previous
#include <cuda_runtime.h>
#include <cuda_fp16.h>
#include <cstdint>

#define BATCH 64
#define TIME  2048
#define FEAT  256
#define MROWS (BATCH * TIME)
#define NTILES (MROWS / 128)    // 1024
#define EPS_V 1e-7f

// ---------------- scratch (static device globals; alloc-free rule) ----------
__device__ __half g_Wh[FEAT * FEAT];             // g_Wh[n*FEAT+k] = (half)W[k][n]
__device__ float  g_part[NTILES * FEAT];         // per-tile numerator partials
__device__ float  g_denp[NTILES];                // per-tile denominator partials

__device__ __forceinline__ uint32_t h2_as_u32(__half2 h) {
    return *reinterpret_cast<uint32_t*>(&h);
}
__device__ __forceinline__ uint32_t smem_u32(const void* p) {
    uint32_t a;
    asm("{ .reg .u64 t; cvta.to.shared.u64 t, %1; cvt.u32.u64 %0, t; }" : "=r"(a) : "l"(p));
    return a;
}
template<int N> __device__ __forceinline__ void cpwait() {
    asm volatile("cp.async.wait_group %0;" :: "n"(N) : "memory");
}

// ---------------- k0: tiled transpose W[k][n] -> g_Wh[n][k] (half) ----------
__global__ __launch_bounds__(1024)
void k0_wh(const float* __restrict__ W) {
    __shared__ float t[32][33];
    const int tx = threadIdx.x, ty = threadIdx.y;
    const int x0 = blockIdx.x * 32, y0 = blockIdx.y * 32;
    t[ty][tx] = W[(y0 + ty) * FEAT + x0 + tx];
    __syncthreads();
    g_Wh[(x0 + ty) * FEAT + y0 + tx] = __float2half_rn(t[tx][ty]);
}

// ---------------- k1: persistent fp16 mma GEMM + fused softmax-numerator ----
#define BM 128
#define BN 256
#define BK 64
#define KT (FEAT / BK)          // 4
#define K1_THREADS 512          // 16 warps: wm = wid%4 (32 M-rows), wn = wid/4 (64 N-cols)

#define STRIDE   144            // smem row bytes; LDSM 8-row phases conflict-free
#define A_BYTES  (BM * STRIDE)            // 18432
#define B_BYTES  (BN * STRIDE)            // 36864
#define STAGE    (A_BYTES + B_BYTES)      // 55296
#define RED_OFF  (2 * STAGE)              // red[512] floats
#define ES_OFF   (RED_OFF + 2048)         // e_s[128]
#define WP_OFF   (ES_OFF + 512)           // wp[4]
#define SMEM_SZ  (WP_OFF + 32)            // 112672

__device__ __forceinline__ void mma_f16(float* d, const uint32_t* a, uint32_t b0, uint32_t b1) {
    asm volatile(
        "mma.sync.aligned.m16n8k16.row.col.f32.f16.f16.f32 "
        "{%0,%1,%2,%3}, {%4,%5,%6,%7}, {%8,%9}, {%0,%1,%2,%3};"
        : "+f"(d[0]), "+f"(d[1]), "+f"(d[2]), "+f"(d[3])
        : "r"(a[0]), "r"(a[1]), "r"(a[2]), "r"(a[3]), "r"(b0), "r"(b1));
}
__device__ __forceinline__ void ldsm4(uint32_t* d, uint32_t addr) {
    asm volatile("ldmatrix.sync.aligned.m8n8.x4.shared.b16 {%0,%1,%2,%3}, [%4];"
                 : "=r"(d[0]), "=r"(d[1]), "=r"(d[2]), "=r"(d[3]) : "r"(addr));
}

// B chunk (256 rows x 64 halfs) into stage s via cp.async; one commit group.
__device__ __forceinline__ void prefB(uint32_t sb, int s, int k0, int tid) {
    const uint32_t base = sb + s * STAGE + A_BYTES;
    #pragma unroll
    for (int i = 0; i < 4; i++) {
        const int ch = tid + i * K1_THREADS;
        const int n = ch >> 3, q = ch & 7;
        asm volatile("cp.async.cg.shared.global [%0], [%1], 16;"
                     :: "r"(base + n * STRIDE + q * 16),
                        "l"(g_Wh + n * FEAT + k0 + q * 8) : "memory");
    }
    asm volatile("cp.async.commit_group;" ::: "memory");
}
// A chunk (128 rows x 64 floats) into registers
__device__ __forceinline__ void ldgA(float4* areg, const float* __restrict__ x,
                                     size_t rowBase, int k0, int tid) {
    #pragma unroll
    for (int i = 0; i < 4; i++) {
        const int f4 = tid + i * K1_THREADS;
        const int row = f4 >> 4, q = f4 & 15;
        areg[i] = *reinterpret_cast<const float4*>(&x[(rowBase + row) * FEAT + k0 + q * 4]);
    }
}

__global__ __launch_bounds__(K1_THREADS, 1)
void k1_mma(const float* __restrict__ x, const float* __restrict__ bias,
            const float* __restrict__ u)
{
    extern __shared__ char smem[];
    const uint32_t sb = smem_u32(smem);
    const int tid = threadIdx.x;
    const int wid = tid >> 5, l = tid & 31;
    const int wm = wid & 3, wn = wid >> 2;
    const int lq = l >> 2, lr = l & 3;

    const uint32_t aOff = (uint32_t)((wm * 32 + (l & 7) + ((l >> 3) & 1) * 8) * STRIDE
                                     + ((l >> 4) & 1) * 16);
    const uint32_t bOff = (uint32_t)(A_BYTES + (wn * 64 + (l & 7) + ((l >> 4) & 1) * 8) * STRIDE
                                     + ((l >> 3) & 1) * 16);

    float* red = reinterpret_cast<float*>(smem + RED_OFF);
    float* e_s = reinterpret_cast<float*>(smem + ES_OFF);
    float* wp  = reinterpret_cast<float*>(smem + WP_OFF);

    float4 areg[4];
    // ---- initial prologue: tile = blockIdx.x, stage 0 ----
    prefB(sb, 0, 0, tid);
    ldgA(areg, x, (size_t)blockIdx.x * BM, 0, tid);

    for (int tile = blockIdx.x; tile < NTILES; tile += gridDim.x) {
        const size_t rowBase = (size_t)tile * BM;
        const int nextTile = tile + gridDim.x;

        float acc[2][8][4];
        #pragma unroll
        for (int mt = 0; mt < 2; mt++)
            #pragma unroll
            for (int nt = 0; nt < 8; nt++)
                #pragma unroll
                for (int c = 0; c < 4; c++) acc[mt][nt][c] = 0.0f;

        #pragma unroll
        for (int kt = 0; kt < KT; kt++) {
            char* Ab = smem + (kt & 1) * STAGE;
            const uint32_t stU = sb + (kt & 1) * STAGE;

            // STS A(kt) from regs (cvt fp32 -> half2)
            #pragma unroll
            for (int i = 0; i < 4; i++) {
                const int f4 = tid + i * K1_THREADS;
                const int row = f4 >> 4, q = f4 & 15;
                uint32_t h0 = h2_as_u32(__floats2half2_rn(areg[i].x, areg[i].y));
                uint32_t h1 = h2_as_u32(__floats2half2_rn(areg[i].z, areg[i].w));
                *reinterpret_cast<uint2*>(Ab + row * STRIDE + q * 8) = make_uint2(h0, h1);
            }
            cpwait<0>();
            __syncthreads();

            // prefetch: next kt of this tile, or kt=0 of next tile
            if (kt < KT - 1) {
                prefB(sb, (kt + 1) & 1, (kt + 1) * BK, tid);
                ldgA(areg, x, rowBase, (kt + 1) * BK, tid);
            } else if (nextTile < NTILES) {
                prefB(sb, 0, 0, tid);
                ldgA(areg, x, (size_t)nextTile * BM, 0, tid);
            }

            // ---- compute: 4 k16-steps via ldmatrix ----
            #pragma unroll
            for (int ks = 0; ks < 4; ks++) {
                uint32_t af[2][4];
                #pragma unroll
                for (int mt = 0; mt < 2; mt++)
                    ldsm4(af[mt], stU + aOff + mt * 16 * STRIDE + ks * 32);
                #pragma unroll
                for (int p = 0; p < 4; p++) {
                    uint32_t bf[4];
                    ldsm4(bf, stU + bOff + p * 16 * STRIDE + ks * 32);
                    #pragma unroll
                    for (int mt = 0; mt < 2; mt++) {
                        mma_f16(acc[mt][2 * p],     af[mt], bf[0], bf[1]);
                        mma_f16(acc[mt][2 * p + 1], af[mt], bf[2], bf[3]);
                    }
                }
            }
            __syncthreads();
        }

        // ---- epilogue stage 1: tanh + u-dot, reduce to per-row ait ---------
        float bv[16], uv[16];
        #pragma unroll
        for (int nt = 0; nt < 8; nt++)
            #pragma unroll
            for (int d = 0; d < 2; d++) {
                const int col = wn * 64 + nt * 8 + lr * 2 + d;
                bv[nt * 2 + d] = bias[col];
                uv[nt * 2 + d] = u[col];
            }

        #pragma unroll
        for (int mt = 0; mt < 2; mt++) {
            float p0 = 0.0f, p1 = 0.0f;
            #pragma unroll
            for (int nt = 0; nt < 8; nt++)
                #pragma unroll
                for (int d = 0; d < 2; d++) {
                    {
                        const float v = acc[mt][nt][d] + bv[nt * 2 + d];
                        const float t = 1.0f - __fdividef(2.0f, __expf(v + v) + 1.0f);
                        p0 = fmaf(t, uv[nt * 2 + d], p0);
                    }
                    {
                        const float v = acc[mt][nt][2 + d] + bv[nt * 2 + d];
                        const float t = 1.0f - __fdividef(2.0f, __expf(v + v) + 1.0f);
                        p1 = fmaf(t, uv[nt * 2 + d], p1);
                    }
                }
            #pragma unroll
            for (int off = 2; off > 0; off >>= 1) {
                p0 += __shfl_xor_sync(0xffffffffu, p0, off);
                p1 += __shfl_xor_sync(0xffffffffu, p1, off);
            }
            if (lr == 0) {
                red[wn * BM + wm * 32 + mt * 16 + lq]     = p0;
                red[wn * BM + wm * 32 + mt * 16 + lq + 8] = p1;
            }
        }
        __syncthreads();

        // ---- epilogue stage 2: e = exp(ait); denominator partial -----------
        if (tid < BM) {
            const float s = red[tid] + red[BM + tid] + red[2 * BM + tid] + red[3 * BM + tid];
            const float e = expf(s);
            e_s[tid] = e;
            float w = e;
            #pragma unroll
            for (int off = 16; off > 0; off >>= 1)
                w += __shfl_xor_sync(0xffffffffu, w, off);
            if (l == 0) wp[wid] = w;
        }
        __syncthreads();
        if (tid == 0)
            g_denp[tile] = wp[0] + wp[1] + wp[2] + wp[3];

        // ---- epilogue stage 3: numerator partial (x tile L2-hot), MLP4 -----
        {
            const int col = tid & 255;
            const int rowgrp = tid >> 8;              // rows 0..63 / 64..127
            const float* xp = x + (rowBase + (size_t)rowgrp * 64) * FEAT + col;
            const float* ep = e_s + rowgrp * 64;
            float a0 = 0.0f, a1 = 0.0f, a2 = 0.0f, a3 = 0.0f;
            #pragma unroll 4
            for (int i = 0; i < 64; i += 4) {
                a0 = fmaf(xp[(size_t)i * FEAT],       ep[i],     a0);
                a1 = fmaf(xp[(size_t)(i + 1) * FEAT], ep[i + 1], a1);
                a2 = fmaf(xp[(size_t)(i + 2) * FEAT], ep[i + 2], a2);
                a3 = fmaf(xp[(size_t)(i + 3) * FEAT], ep[i + 3], a3);
            }
            red[tid] = (a0 + a1) + (a2 + a3);
        }
        __syncthreads();
        if (tid < FEAT)
            g_part[tile * FEAT + tid] = red[tid] + red[FEAT + tid];
    }
}

// ---------------- k_final: out[b,f] = num/(den+eps) -------------------------
#define CTAS_PER_B (TIME / BM)   // 16
__global__ __launch_bounds__(256)
void k_final(float* __restrict__ out) {
    const int b = blockIdx.x, tid = threadIdx.x;
    float den = 0.0f;
    #pragma unroll
    for (int i = 0; i < CTAS_PER_B; i++)
        den += g_denp[b * CTAS_PER_B + i];
    float num = 0.0f;
    #pragma unroll
    for (int i = 0; i < CTAS_PER_B; i++)
        num += g_part[(b * CTAS_PER_B + i) * FEAT + tid];
    out[b * FEAT + tid] = num / (den + EPS_V);
}

// ---------------------------------------------------------------------------
extern "C" void kernel_launch(void* const* d_in, const int* in_sizes, int n_in,
                              void* d_out, int out_size) {
    const float* x = (const float*)d_in[0];
    const float* W = (const float*)d_in[1];
    const float* b = (const float*)d_in[2];
    const float* u = (const float*)d_in[3];
    float* out = (float*)d_out;

    int nsm = 0;
    cudaDeviceGetAttribute(&nsm, cudaDevAttrMultiProcessorCount, 0);
    if (nsm <= 0 || nsm > NTILES) nsm = 148;

    cudaFuncSetAttribute(k1_mma, cudaFuncAttributeMaxDynamicSharedMemorySize, SMEM_SZ);

    dim3 tb(32, 32);
    dim3 tg(FEAT / 32, FEAT / 32);
    k0_wh<<<tg, tb>>>(W);
    k1_mma<<<nsm, K1_THREADS, SMEM_SZ>>>(x, b, u);
    k_final<<<BATCH, FEAT>>>(out);
}

// round 17
// speedup vs baseline: 1.1380x; 1.0459x over previous
#include <cuda_runtime.h>
#include <cuda_fp16.h>
#include <cstdint>

#define BATCH 64
#define TIME  2048
#define FEAT  256
#define MROWS (BATCH * TIME)
#define NTILES (MROWS / 128)    // 1024
#define EPS_V 1e-7f

// ---------------- scratch (static device globals; alloc-free rule) ----------
__device__ __half g_Wh[FEAT * FEAT];             // g_Wh[n*FEAT+k] = (half)W[k][n]
__device__ float  g_part[NTILES * FEAT];         // per-tile numerator partials
__device__ float  g_denp[NTILES];                // per-tile denominator partials

__device__ __forceinline__ uint32_t h2_as_u32(__half2 h) {
    return *reinterpret_cast<uint32_t*>(&h);
}
__device__ __forceinline__ uint32_t smem_u32(const void* p) {
    uint32_t a;
    asm("{ .reg .u64 t; cvta.to.shared.u64 t, %1; cvt.u32.u64 %0, t; }" : "=r"(a) : "l"(p));
    return a;
}
template<int N> __device__ __forceinline__ void cpwait() {
    asm volatile("cp.async.wait_group %0;" :: "n"(N) : "memory");
}

// ---------------- k0: tiled transpose W[k][n] -> g_Wh[n][k] (half) ----------
__global__ __launch_bounds__(1024)
void k0_wh(const float* __restrict__ W) {
    __shared__ float t[32][33];
    const int tx = threadIdx.x, ty = threadIdx.y;
    const int x0 = blockIdx.x * 32, y0 = blockIdx.y * 32;
    t[ty][tx] = W[(y0 + ty) * FEAT + x0 + tx];
    __syncthreads();
    g_Wh[(x0 + ty) * FEAT + y0 + tx] = __float2half_rn(t[tx][ty]);
}

// ---------------- k1: persistent fp16 mma GEMM + fused softmax-numerator ----
#define BM 128
#define BN 256
#define BK 64
#define KT (FEAT / BK)          // 4
#define K1_THREADS 512          // 16 warps: wm = wid%4 (32 M-rows), wn = wid/4 (64 N-cols)

#define STRIDE   144            // smem row bytes; LDSM 8-row phases conflict-free
#define A_BYTES  (BM * STRIDE)            // 18432
#define B_BYTES  (BN * STRIDE)            // 36864
#define STAGE    (A_BYTES + B_BYTES)      // 55296
#define RED_OFF  (2 * STAGE)              // red2[1024] floats (4096B)
#define ES_OFF   (RED_OFF + 4096)         // e_s[128]
#define WP_OFF   (ES_OFF + 512)           // wp[4]
#define ARC_STR  520                      // archive row stride (bytes)
#define ARC_OFF  (WP_OFF + 32)            // 115232, 16B aligned
#define SMEM_SZ  (ARC_OFF + BM * ARC_STR) // 181792

__device__ __forceinline__ void mma_f16(float* d, const uint32_t* a, uint32_t b0, uint32_t b1) {
    asm volatile(
        "mma.sync.aligned.m16n8k16.row.col.f32.f16.f16.f32 "
        "{%0,%1,%2,%3}, {%4,%5,%6,%7}, {%8,%9}, {%0,%1,%2,%3};"
        : "+f"(d[0]), "+f"(d[1]), "+f"(d[2]), "+f"(d[3])
        : "r"(a[0]), "r"(a[1]), "r"(a[2]), "r"(a[3]), "r"(b0), "r"(b1));
}
__device__ __forceinline__ void ldsm4(uint32_t* d, uint32_t addr) {
    asm volatile("ldmatrix.sync.aligned.m8n8.x4.shared.b16 {%0,%1,%2,%3}, [%4];"
                 : "=r"(d[0]), "=r"(d[1]), "=r"(d[2]), "=r"(d[3]) : "r"(addr));
}

// B chunk (256 rows x 64 halfs) into stage s via cp.async; one commit group.
__device__ __forceinline__ void prefB(uint32_t sb, int s, int k0, int tid) {
    const uint32_t base = sb + s * STAGE + A_BYTES;
    #pragma unroll
    for (int i = 0; i < 4; i++) {
        const int ch = tid + i * K1_THREADS;
        const int n = ch >> 3, q = ch & 7;
        asm volatile("cp.async.cg.shared.global [%0], [%1], 16;"
                     :: "r"(base + n * STRIDE + q * 16),
                        "l"(g_Wh + n * FEAT + k0 + q * 8) : "memory");
    }
    asm volatile("cp.async.commit_group;" ::: "memory");
}
// A chunk (128 rows x 64 floats) into registers
__device__ __forceinline__ void ldgA(float4* areg, const float* __restrict__ x,
                                     size_t rowBase, int k0, int tid) {
    #pragma unroll
    for (int i = 0; i < 4; i++) {
        const int f4 = tid + i * K1_THREADS;
        const int row = f4 >> 4, q = f4 & 15;
        areg[i] = *reinterpret_cast<const float4*>(&x[(rowBase + row) * FEAT + k0 + q * 4]);
    }
}

__global__ __launch_bounds__(K1_THREADS, 1)
void k1_mma(const float* __restrict__ x, const float* __restrict__ bias,
            const float* __restrict__ u)
{
    extern __shared__ char smem[];
    const uint32_t sb = smem_u32(smem);
    const int tid = threadIdx.x;
    const int wid = tid >> 5, l = tid & 31;
    const int wm = wid & 3, wn = wid >> 2;
    const int lq = l >> 2, lr = l & 3;

    const uint32_t aOff = (uint32_t)((wm * 32 + (l & 7) + ((l >> 3) & 1) * 8) * STRIDE
                                     + ((l >> 4) & 1) * 16);
    const uint32_t bOff = (uint32_t)(A_BYTES + (wn * 64 + (l & 7) + ((l >> 4) & 1) * 8) * STRIDE
                                     + ((l >> 3) & 1) * 16);

    float* red2 = reinterpret_cast<float*>(smem + RED_OFF);   // 1024 floats
    float* e_s  = reinterpret_cast<float*>(smem + ES_OFF);
    float* wp   = reinterpret_cast<float*>(smem + WP_OFF);

    float4 areg[4];
    // ---- initial prologue: tile = blockIdx.x, stage 0 ----
    prefB(sb, 0, 0, tid);
    ldgA(areg, x, (size_t)blockIdx.x * BM, 0, tid);

    for (int tile = blockIdx.x; tile < NTILES; tile += gridDim.x) {
        const size_t rowBase = (size_t)tile * BM;
        const int nextTile = tile + gridDim.x;

        float acc[2][8][4];
        #pragma unroll
        for (int mt = 0; mt < 2; mt++)
            #pragma unroll
            for (int nt = 0; nt < 8; nt++)
                #pragma unroll
                for (int c = 0; c < 4; c++) acc[mt][nt][c] = 0.0f;

        #pragma unroll
        for (int kt = 0; kt < KT; kt++) {
            char* Ab = smem + (kt & 1) * STAGE;
            const uint32_t stU = sb + (kt & 1) * STAGE;

            // STS A(kt) from regs (cvt fp32 -> half2), double-store to archive
            #pragma unroll
            for (int i = 0; i < 4; i++) {
                const int f4 = tid + i * K1_THREADS;
                const int row = f4 >> 4, q = f4 & 15;
                uint32_t h0 = h2_as_u32(__floats2half2_rn(areg[i].x, areg[i].y));
                uint32_t h1 = h2_as_u32(__floats2half2_rn(areg[i].z, areg[i].w));
                const uint2 hv = make_uint2(h0, h1);
                *reinterpret_cast<uint2*>(Ab + row * STRIDE + q * 8) = hv;
                *reinterpret_cast<uint2*>(smem + ARC_OFF + row * ARC_STR
                                          + kt * 128 + q * 8) = hv;
            }
            cpwait<0>();
            __syncthreads();

            // prefetch: next kt of this tile, or kt=0 of next tile
            if (kt < KT - 1) {
                prefB(sb, (kt + 1) & 1, (kt + 1) * BK, tid);
                ldgA(areg, x, rowBase, (kt + 1) * BK, tid);
            } else if (nextTile < NTILES) {
                prefB(sb, 0, 0, tid);
                ldgA(areg, x, (size_t)nextTile * BM, 0, tid);
            }

            // ---- compute: 4 k16-steps via ldmatrix ----
            #pragma unroll
            for (int ks = 0; ks < 4; ks++) {
                uint32_t af[2][4];
                #pragma unroll
                for (int mt = 0; mt < 2; mt++)
                    ldsm4(af[mt], stU + aOff + mt * 16 * STRIDE + ks * 32);
                #pragma unroll
                for (int p = 0; p < 4; p++) {
                    uint32_t bf[4];
                    ldsm4(bf, stU + bOff + p * 16 * STRIDE + ks * 32);
                    #pragma unroll
                    for (int mt = 0; mt < 2; mt++) {
                        mma_f16(acc[mt][2 * p],     af[mt], bf[0], bf[1]);
                        mma_f16(acc[mt][2 * p + 1], af[mt], bf[2], bf[3]);
                    }
                }
            }
            __syncthreads();
        }

        // ---- epilogue stage 1: tanh + u-dot, reduce to per-row ait ---------
        float bv[16], uv[16];
        #pragma unroll
        for (int nt = 0; nt < 8; nt++)
            #pragma unroll
            for (int d = 0; d < 2; d++) {
                const int col = wn * 64 + nt * 8 + lr * 2 + d;
                bv[nt * 2 + d] = bias[col];
                uv[nt * 2 + d] = u[col];
            }

        #pragma unroll
        for (int mt = 0; mt < 2; mt++) {
            float p0 = 0.0f, p1 = 0.0f;
            #pragma unroll
            for (int nt = 0; nt < 8; nt++)
                #pragma unroll
                for (int d = 0; d < 2; d++) {
                    {
                        const float v = acc[mt][nt][d] + bv[nt * 2 + d];
                        const float t = 1.0f - __fdividef(2.0f, __expf(v + v) + 1.0f);
                        p0 = fmaf(t, uv[nt * 2 + d], p0);
                    }
                    {
                        const float v = acc[mt][nt][2 + d] + bv[nt * 2 + d];
                        const float t = 1.0f - __fdividef(2.0f, __expf(v + v) + 1.0f);
                        p1 = fmaf(t, uv[nt * 2 + d], p1);
                    }
                }
            #pragma unroll
            for (int off = 2; off > 0; off >>= 1) {
                p0 += __shfl_xor_sync(0xffffffffu, p0, off);
                p1 += __shfl_xor_sync(0xffffffffu, p1, off);
            }
            if (lr == 0) {
                red2[wn * BM + wm * 32 + mt * 16 + lq]     = p0;
                red2[wn * BM + wm * 32 + mt * 16 + lq + 8] = p1;
            }
        }
        __syncthreads();

        // ---- epilogue stage 2: e = exp(ait); denominator partial -----------
        if (tid < BM) {
            const float s = red2[tid] + red2[BM + tid] + red2[2 * BM + tid] + red2[3 * BM + tid];
            const float e = expf(s);
            e_s[tid] = e;
            float w = e;
            #pragma unroll
            for (int off = 16; off > 0; off >>= 1)
                w += __shfl_xor_sync(0xffffffffu, w, off);
            if (l == 0) wp[wid] = w;
        }
        __syncthreads();
        if (tid == 0)
            g_denp[tile] = wp[0] + wp[1] + wp[2] + wp[3];

        // ---- epilogue stage 3: numerator from smem ARCHIVE (no gmem) -------
        // thread owns col-pair cp (cols 2cp,2cp+1) over 32 rows (group grp)
        {
            const int cp  = tid & 127;        // 0..127
            const int grp = tid >> 7;         // 0..3 -> rows grp*32..+31
            const char* ap = smem + ARC_OFF + (grp * 32) * ARC_STR + cp * 4;
            const float* ep = e_s + grp * 32;
            float a0 = 0.0f, a1 = 0.0f;
            #pragma unroll 8
            for (int i = 0; i < 32; i++) {
                const __half2 h = *reinterpret_cast<const __half2*>(ap + i * ARC_STR);
                const float2 f2 = __half22float2(h);
                const float e = ep[i];
                a0 = fmaf(f2.x, e, a0);
                a1 = fmaf(f2.y, e, a1);
            }
            __syncthreads();   // stage-1/2 red2 reads done before overwrite
            reinterpret_cast<float2*>(red2)[grp * 128 + cp] = make_float2(a0, a1);
        }
        __syncthreads();
        if (tid < FEAT)
            g_part[tile * FEAT + tid] = (red2[tid] + red2[256 + tid])
                                      + (red2[512 + tid] + red2[768 + tid]);
        __syncthreads();   // protect red2/e_s/archive before next tile writes
    }
}

// ---------------- k_final: out[b,f] = num/(den+eps) -------------------------
#define CTAS_PER_B (TIME / BM)   // 16
__global__ __launch_bounds__(256)
void k_final(float* __restrict__ out) {
    const int b = blockIdx.x, tid = threadIdx.x;
    float den = 0.0f;
    #pragma unroll
    for (int i = 0; i < CTAS_PER_B; i++)
        den += g_denp[b * CTAS_PER_B + i];
    float num = 0.0f;
    #pragma unroll
    for (int i = 0; i < CTAS_PER_B; i++)
        num += g_part[(b * CTAS_PER_B + i) * FEAT + tid];
    out[b * FEAT + tid] = num / (den + EPS_V);
}

// ---------------------------------------------------------------------------
extern "C" void kernel_launch(void* const* d_in, const int* in_sizes, int n_in,
                              void* d_out, int out_size) {
    const float* x = (const float*)d_in[0];
    const float* W = (const float*)d_in[1];
    const float* b = (const float*)d_in[2];
    const float* u = (const float*)d_in[3];
    float* out = (float*)d_out;

    int nsm = 0;
    cudaDeviceGetAttribute(&nsm, cudaDevAttrMultiProcessorCount, 0);
    if (nsm <= 0 || nsm > NTILES) nsm = 148;

    cudaFuncSetAttribute(k1_mma, cudaFuncAttributeMaxDynamicSharedMemorySize, SMEM_SZ);

    dim3 tb(32, 32);
    dim3 tg(FEAT / 32, FEAT / 32);
    k0_wh<<<tg, tb>>>(W);
    k1_mma<<<nsm, K1_THREADS, SMEM_SZ>>>(x, b, u);
    k_final<<<BATCH, FEAT>>>(out);
}